// round 14
// baseline (speedup 1.0000x reference)
#include <cuda_runtime.h>
#include <cuda_bf16.h>
#include <math.h>
#include <stdint.h>

// NTXent — Round 14: R13 + float2-vectorized prep/finalize side paths.
//  hmma: R8 verbatim (128x128 CTA, 4 warps of 64x64, BK=32, 3-stage
//        wait_group 1, refill AFTER compute). Computes sum_j exp(4*S_ij).
//  diag & row-sums: exact fp32 rank-1 paths (q = sum_j p_hat_j).

#define B_SIZE 8192
#define D_SIZE 626
#define D2     313                    // D_SIZE / 2 exactly
#define KPAD   640
#define K2     320
#define INV_TEMP 4.0f

#define BM 128
#define BN 128
#define BK 32
#define NITER (KPAD / BK)             // 20
#define STAGES 3
#define ROWB 80                        // 32 bf16 + 8B pad
#define STAGE_BYTES (2 * BM * ROWB)    // 20480
#define SMEM_BYTES (STAGES * STAGE_BYTES)   // 61440

// ---------------- persistent scratch ---------------------------------------
__device__ __align__(128) __nv_bfloat16 g_Ab[B_SIZE * KPAD];
__device__ __align__(128) __nv_bfloat16 g_Pb[B_SIZE * KPAD];
__device__ float g_rna[B_SIZE];
__device__ float g_sumexp[B_SIZE];
__device__ float g_diag[B_SIZE];
__device__ __align__(8) float g_q[KPAD];   // padded so float2 reads are safe

// ---------------- helpers ---------------------------------------------------
__device__ __forceinline__ uint32_t smem_u32(const void* p) {
    uint32_t a;
    asm("{ .reg .u64 t; cvta.to.shared.u64 t, %1; cvt.u32.u64 %0, t; }"
        : "=r"(a) : "l"(p));
    return a;
}
__device__ __forceinline__ void cp16(uint32_t dst, const void* src) {
    asm volatile("cp.async.cg.shared.global [%0], [%1], 16;" :: "r"(dst), "l"(src));
}
__device__ __forceinline__ void ldsm_x4(uint32_t* r, uint32_t addr) {
    asm volatile("ldmatrix.sync.aligned.m8n8.x4.shared.b16 {%0,%1,%2,%3}, [%4];"
                 : "=r"(r[0]), "=r"(r[1]), "=r"(r[2]), "=r"(r[3]) : "r"(addr));
}
__device__ __forceinline__ void mma_bf16(float* c, const uint32_t* a,
                                         uint32_t b0, uint32_t b1) {
    asm volatile(
        "mma.sync.aligned.m16n8k16.row.col.f32.bf16.bf16.f32 "
        "{%0,%1,%2,%3}, {%4,%5,%6,%7}, {%8,%9}, {%0,%1,%2,%3};"
        : "+f"(c[0]), "+f"(c[1]), "+f"(c[2]), "+f"(c[3])
        : "r"(a[0]), "r"(a[1]), "r"(a[2]), "r"(a[3]), "r"(b0), "r"(b1));
}

// ---------------------------------------------------------------------------
// zeroq
// ---------------------------------------------------------------------------
__global__ void ntxent_zeroq() {
    if (threadIdx.x < KPAD) g_q[threadIdx.x] = 0.f;
}

// ---------------------------------------------------------------------------
// prep: norms, exact fp32 diag, normalized bf16 copies, fused q accumulation.
// float2 everywhere (row stride 2504 B is 8-aligned; 626 = 2*313 exact).
// grid B/8, block 256; one warp per row.
// ---------------------------------------------------------------------------
__global__ void __launch_bounds__(256) ntxent_prep(const float* __restrict__ A,
                                                   const float* __restrict__ P,
                                                   float* __restrict__ out) {
    __shared__ __align__(8) float qacc[D_SIZE + 1];   // pad to even
    for (int c = threadIdx.x; c < D_SIZE + 1; c += 256) qacc[c] = 0.f;
    __syncthreads();

    const int warp = threadIdx.x >> 5;
    const int lane = threadIdx.x & 31;
    const int row  = blockIdx.x * 8 + warp;

    const float2* ar2 = (const float2*)(A + (size_t)row * D_SIZE);
    const float2* pr2 = (const float2*)(P + (size_t)row * D_SIZE);

    float ssa0 = 0.f, ssa1 = 0.f, ssp0 = 0.f, ssp1 = 0.f, dt0 = 0.f, dt1 = 0.f;
    for (int c2 = lane; c2 < D2; c2 += 32) {
        float2 av = ar2[c2], pv = pr2[c2];
        ssa0 = fmaf(av.x, av.x, ssa0);
        ssa1 = fmaf(av.y, av.y, ssa1);
        ssp0 = fmaf(pv.x, pv.x, ssp0);
        ssp1 = fmaf(pv.y, pv.y, ssp1);
        dt0  = fmaf(av.x, pv.x, dt0);
        dt1  = fmaf(av.y, pv.y, dt1);
    }
    float ssa = ssa0 + ssa1, ssp = ssp0 + ssp1, dot = dt0 + dt1;
    #pragma unroll
    for (int o = 16; o; o >>= 1) {
        ssa += __shfl_xor_sync(0xffffffffu, ssa, o);
        ssp += __shfl_xor_sync(0xffffffffu, ssp, o);
        dot += __shfl_xor_sync(0xffffffffu, dot, o);
    }
    const float rna = rsqrtf(ssa);
    const float rnp = rsqrtf(ssp);

    __nv_bfloat162* ya2 = (__nv_bfloat162*)(g_Ab + (size_t)row * KPAD);
    __nv_bfloat162* yp2 = (__nv_bfloat162*)(g_Pb + (size_t)row * KPAD);
    float2* qa2 = (float2*)qacc;
    for (int c2 = lane; c2 < K2; c2 += 32) {
        float2 av, pv;
        if (c2 < D2) { av = ar2[c2]; pv = pr2[c2]; }
        else         { av = make_float2(0.f, 0.f); pv = av; }
        float2 avn = make_float2(av.x * rna, av.y * rna);
        float2 pvn = make_float2(pv.x * rnp, pv.y * rnp);
        ya2[c2] = __float22bfloat162_rn(avn);
        yp2[c2] = __float22bfloat162_rn(pvn);
        if (c2 < D2) {
            atomicAdd(&qa2[c2].x, pvn.x);
            atomicAdd(&qa2[c2].y, pvn.y);
        }
    }
    if (lane == 0) {
        g_rna[row]    = rna;
        g_diag[row]   = dot * rna * rnp;
        g_sumexp[row] = 0.f;
    }
    __syncthreads();
    for (int c = threadIdx.x; c < D_SIZE; c += 256)
        atomicAdd(&g_q[c], qacc[c]);
    if (blockIdx.x == 0 && threadIdx.x < 3) out[threadIdx.x] = 0.f;
}

// ---------------------------------------------------------------------------
// stage loader (128 threads): 128x32 A + 128x32 B bf16, 16B cp.async each
// ---------------------------------------------------------------------------
__device__ __forceinline__ void load_stage(uint32_t sbase, int m0, int n0,
                                           int k0, int tid) {
    const char* asrc = (const char*)g_Ab + ((size_t)m0 * KPAD + k0) * 2;
    const char* bsrc = (const char*)g_Pb + ((size_t)n0 * KPAD + k0) * 2;
    #pragma unroll
    for (int i = 0; i < 4; i++) {
        int seg = tid + i * 128, row = seg >> 2, g = seg & 3;
        cp16(sbase + row * ROWB + g * 16, asrc + (size_t)row * (KPAD * 2) + g * 16);
    }
    #pragma unroll
    for (int i = 0; i < 4; i++) {
        int seg = tid + i * 128, row = seg >> 2, g = seg & 3;
        cp16(sbase + BM * ROWB + row * ROWB + g * 16,
             bsrc + (size_t)row * (KPAD * 2) + g * 16);
    }
    asm volatile("cp.async.commit_group;" ::: "memory");
}

// ---------------------------------------------------------------------------
// main: 128x128 tile, 4 warps (64x64), BK=32, 3-stage (wait_group 1),
// refill AFTER compute (R8 verbatim)
// ---------------------------------------------------------------------------
__global__ void __launch_bounds__(128) ntxent_hmma() {
    extern __shared__ char smem[];
    const uint32_t sbase = smem_u32(smem);

    const int tid  = threadIdx.x;
    const int lane = tid & 31;
    const int wid  = tid >> 5;
    const int wm   = wid >> 1;
    const int wn   = wid & 1;
    const int m0   = blockIdx.y * BM;
    const int n0   = blockIdx.x * BN;

    float acc[4][8][4];
    #pragma unroll
    for (int i = 0; i < 4; i++)
        #pragma unroll
        for (int j = 0; j < 8; j++)
            #pragma unroll
            for (int q = 0; q < 4; q++) acc[i][j][q] = 0.f;

    const int a_row  = lane & 15;
    const int a_koff = ((lane >> 4) & 1) * 16;
    const int b_n    = (lane & 7) | ((lane >> 1) & 8);
    const int b_koff = ((lane >> 3) & 1) * 16;
    const uint32_t aBase = sbase + (wm * 64 + a_row) * ROWB + a_koff;
    const uint32_t bBase = sbase + BM * ROWB + (wn * 64 + b_n) * ROWB + b_koff;

    load_stage(sbase,               m0, n0, 0,  tid);
    load_stage(sbase + STAGE_BYTES, m0, n0, BK, tid);

    uint32_t soff = 0;
    uint32_t loff = 2 * STAGE_BYTES;
    int      lk   = 2 * BK;

    for (int c = 0; c < NITER; c++) {
        if (c < NITER - 1) asm volatile("cp.async.wait_group 1;" ::: "memory");
        else               asm volatile("cp.async.wait_group 0;" ::: "memory");
        __syncthreads();

        #pragma unroll
        for (int ks = 0; ks < 2; ks++) {
            const uint32_t koff = soff + ks * 32;

            uint32_t afrag[4][4];
            #pragma unroll
            for (int mi = 0; mi < 4; mi++)
                ldsm_x4(afrag[mi], aBase + koff + mi * (16 * ROWB));

            uint32_t bfrag[4][4];
            #pragma unroll
            for (int np = 0; np < 4; np++)
                ldsm_x4(bfrag[np], bBase + koff + np * (16 * ROWB));

            #pragma unroll
            for (int mi = 0; mi < 4; mi++)
                #pragma unroll
                for (int np = 0; np < 4; np++) {
                    mma_bf16(acc[mi][np * 2 + 0], afrag[mi],
                             bfrag[np][0], bfrag[np][1]);
                    mma_bf16(acc[mi][np * 2 + 1], afrag[mi],
                             bfrag[np][2], bfrag[np][3]);
                }
        }

        if (c + 2 < NITER) {
            load_stage(sbase + loff, m0, n0, lk, tid);
            lk += BK;
            loff += STAGE_BYTES;
            if (loff == STAGES * STAGE_BYTES) loff = 0;
        }
        soff += STAGE_BYTES;
        if (soff == STAGES * STAGE_BYTES) soff = 0;
    }

    // ---- epilogue: per-row sum of exp(4*S) ----
    float esum[8];
    #pragma unroll
    for (int q = 0; q < 8; q++) esum[q] = 0.f;

    #pragma unroll
    for (int mi = 0; mi < 4; mi++)
        #pragma unroll
        for (int nt = 0; nt < 8; nt++) {
            const float* cc = acc[mi][nt];
            esum[mi * 2 + 0] += __expf(INV_TEMP * cc[0]) + __expf(INV_TEMP * cc[1]);
            esum[mi * 2 + 1] += __expf(INV_TEMP * cc[2]) + __expf(INV_TEMP * cc[3]);
        }
    #pragma unroll
    for (int q = 0; q < 8; q++)
        #pragma unroll
        for (int o = 1; o < 4; o <<= 1)
            esum[q] += __shfl_xor_sync(0xffffffffu, esum[q], o);
    if ((lane & 3) == 0) {
        #pragma unroll
        for (int q = 0; q < 8; q++) {
            const int row = m0 + wm * 64 + (q >> 1) * 16 + (q & 1) * 8 + (lane >> 2);
            atomicAdd(&g_sumexp[row], esum[q]);
        }
    }
}

// ---------------------------------------------------------------------------
// finalize (rowsum fused, float2): one warp per row; block-reduce to out
// ---------------------------------------------------------------------------
__global__ void __launch_bounds__(256) ntxent_finalize(const float* __restrict__ A,
                                                       float* __restrict__ out) {
    const int warp = threadIdx.x >> 5;
    const int lane = threadIdx.x & 31;
    const int row  = blockIdx.x * 8 + warp;

    const float2* ar2 = (const float2*)(A + (size_t)row * D_SIZE);
    const float2* q2  = (const float2*)g_q;
    float d0 = 0.f, d1 = 0.f;
    for (int c2 = lane; c2 < D2; c2 += 32) {
        float2 av = ar2[c2], qv = q2[c2];
        d0 = fmaf(av.x, qv.x, d0);
        d1 = fmaf(av.y, qv.y, d1);
    }
    float d = d0 + d1;
    #pragma unroll
    for (int o = 16; o; o >>= 1) d += __shfl_xor_sync(0xffffffffu, d, o);

    float loss = 0.f, pos = 0.f, neg = 0.f;
    if (lane == 0) {
        const float diag = g_diag[row];
        const float sumS = d * g_rna[row];
        loss = logf(g_sumexp[row]) - INV_TEMP * diag;
        pos  = diag;
        neg  = (sumS - diag) * (1.0f / (float)(B_SIZE - 1));
    }

    __shared__ float sl[8], sp[8], sn[8];
    if (lane == 0) { sl[warp] = loss; sp[warp] = pos; sn[warp] = neg; }
    __syncthreads();
    if (threadIdx.x == 0) {
        float tl = 0.f, tp = 0.f, tg = 0.f;
        #pragma unroll
        for (int w = 0; w < 8; w++) { tl += sl[w]; tp += sp[w]; tg += sn[w]; }
        const float invB = 1.0f / (float)B_SIZE;
        atomicAdd(out + 0, tl * invB);
        atomicAdd(out + 1, tp * invB);
        atomicAdd(out + 2, tg * invB);
    }
}

// ---------------------------------------------------------------------------
extern "C" void kernel_launch(void* const* d_in, const int* in_sizes, int n_in,
                              void* d_out, int out_size) {
    const float* A = (const float*)d_in[0];
    const float* P = (const float*)d_in[1];
    float* out = (float*)d_out;

    cudaFuncSetAttribute(ntxent_hmma,
                         cudaFuncAttributeMaxDynamicSharedMemorySize, SMEM_BYTES);

    ntxent_zeroq<<<1, 1024>>>();
    ntxent_prep<<<B_SIZE / 8, 256>>>(A, P, out);

    dim3 gg(B_SIZE / BN, B_SIZE / BM);   // (64, 64)
    ntxent_hmma<<<gg, 128, SMEM_BYTES>>>();

    ntxent_finalize<<<B_SIZE / 8, 256>>>(A, out);
}

// round 15
// speedup vs baseline: 1.5249x; 1.5249x over previous
#include <cuda_runtime.h>
#include <cuda_bf16.h>
#include <math.h>
#include <stdint.h>

// NTXent — Round 15: bisect of R14 regression.
//  prep: reverted to R13 scalar version (R14's float2 prep suspected culprit).
//  finalize: keeps R14's float2 version (measured 18.2 -> 16.6 us).
//  hmma: R8 verbatim. zeroq unchanged.

#define B_SIZE 8192
#define D_SIZE 626
#define D2     313
#define KPAD   640
#define INV_TEMP 4.0f

#define BM 128
#define BN 128
#define BK 32
#define NITER (KPAD / BK)             // 20
#define STAGES 3
#define ROWB 80                        // 32 bf16 + 8B pad
#define STAGE_BYTES (2 * BM * ROWB)    // 20480
#define SMEM_BYTES (STAGES * STAGE_BYTES)   // 61440

// ---------------- persistent scratch ---------------------------------------
__device__ __align__(128) __nv_bfloat16 g_Ab[B_SIZE * KPAD];
__device__ __align__(128) __nv_bfloat16 g_Pb[B_SIZE * KPAD];
__device__ float g_rna[B_SIZE];
__device__ float g_sumexp[B_SIZE];
__device__ float g_diag[B_SIZE];
__device__ __align__(8) float g_q[KPAD];   // padded: float2 reads safe

// ---------------- helpers ---------------------------------------------------
__device__ __forceinline__ uint32_t smem_u32(const void* p) {
    uint32_t a;
    asm("{ .reg .u64 t; cvta.to.shared.u64 t, %1; cvt.u32.u64 %0, t; }"
        : "=r"(a) : "l"(p));
    return a;
}
__device__ __forceinline__ void cp16(uint32_t dst, const void* src) {
    asm volatile("cp.async.cg.shared.global [%0], [%1], 16;" :: "r"(dst), "l"(src));
}
__device__ __forceinline__ void ldsm_x4(uint32_t* r, uint32_t addr) {
    asm volatile("ldmatrix.sync.aligned.m8n8.x4.shared.b16 {%0,%1,%2,%3}, [%4];"
                 : "=r"(r[0]), "=r"(r[1]), "=r"(r[2]), "=r"(r[3]) : "r"(addr));
}
__device__ __forceinline__ void mma_bf16(float* c, const uint32_t* a,
                                         uint32_t b0, uint32_t b1) {
    asm volatile(
        "mma.sync.aligned.m16n8k16.row.col.f32.bf16.bf16.f32 "
        "{%0,%1,%2,%3}, {%4,%5,%6,%7}, {%8,%9}, {%0,%1,%2,%3};"
        : "+f"(c[0]), "+f"(c[1]), "+f"(c[2]), "+f"(c[3])
        : "r"(a[0]), "r"(a[1]), "r"(a[2]), "r"(a[3]), "r"(b0), "r"(b1));
}

// ---------------------------------------------------------------------------
// zeroq
// ---------------------------------------------------------------------------
__global__ void ntxent_zeroq() {
    if (threadIdx.x < KPAD) g_q[threadIdx.x] = 0.f;
}

// ---------------------------------------------------------------------------
// prep (R13 verbatim): norms, exact fp32 diag, normalized bf16 copies,
// fused q accumulation. grid B/8, block 256; one warp per row.
// ---------------------------------------------------------------------------
__global__ void __launch_bounds__(256) ntxent_prep(const float* __restrict__ A,
                                                   const float* __restrict__ P,
                                                   float* __restrict__ out) {
    __shared__ float qacc[D_SIZE];
    for (int c = threadIdx.x; c < D_SIZE; c += 256) qacc[c] = 0.f;
    __syncthreads();

    const int warp = threadIdx.x >> 5;
    const int lane = threadIdx.x & 31;
    const int row  = blockIdx.x * 8 + warp;

    const float* ar = A + (size_t)row * D_SIZE;
    const float* pr = P + (size_t)row * D_SIZE;
    float ssa = 0.f, ssp = 0.f, dot = 0.f;
    for (int c = lane; c < D_SIZE; c += 32) {
        float av = ar[c], pv = pr[c];
        ssa = fmaf(av, av, ssa);
        ssp = fmaf(pv, pv, ssp);
        dot = fmaf(av, pv, dot);
    }
    #pragma unroll
    for (int o = 16; o; o >>= 1) {
        ssa += __shfl_xor_sync(0xffffffffu, ssa, o);
        ssp += __shfl_xor_sync(0xffffffffu, ssp, o);
        dot += __shfl_xor_sync(0xffffffffu, dot, o);
    }
    const float rna = rsqrtf(ssa);
    const float rnp = rsqrtf(ssp);

    __nv_bfloat16* ya = g_Ab + (size_t)row * KPAD;
    __nv_bfloat16* yp = g_Pb + (size_t)row * KPAD;
    for (int c = lane; c < KPAD; c += 32) {
        float av = (c < D_SIZE) ? ar[c] * rna : 0.f;
        float pv = (c < D_SIZE) ? pr[c] * rnp : 0.f;
        ya[c] = __float2bfloat16(av);
        yp[c] = __float2bfloat16(pv);
        if (c < D_SIZE) atomicAdd(&qacc[c], pv);
    }
    if (lane == 0) {
        g_rna[row]    = rna;
        g_diag[row]   = dot * rna * rnp;
        g_sumexp[row] = 0.f;
    }
    __syncthreads();
    for (int c = threadIdx.x; c < D_SIZE; c += 256)
        atomicAdd(&g_q[c], qacc[c]);
    if (blockIdx.x == 0 && threadIdx.x < 3) out[threadIdx.x] = 0.f;
}

// ---------------------------------------------------------------------------
// stage loader (128 threads): 128x32 A + 128x32 B bf16, 16B cp.async each
// ---------------------------------------------------------------------------
__device__ __forceinline__ void load_stage(uint32_t sbase, int m0, int n0,
                                           int k0, int tid) {
    const char* asrc = (const char*)g_Ab + ((size_t)m0 * KPAD + k0) * 2;
    const char* bsrc = (const char*)g_Pb + ((size_t)n0 * KPAD + k0) * 2;
    #pragma unroll
    for (int i = 0; i < 4; i++) {
        int seg = tid + i * 128, row = seg >> 2, g = seg & 3;
        cp16(sbase + row * ROWB + g * 16, asrc + (size_t)row * (KPAD * 2) + g * 16);
    }
    #pragma unroll
    for (int i = 0; i < 4; i++) {
        int seg = tid + i * 128, row = seg >> 2, g = seg & 3;
        cp16(sbase + BM * ROWB + row * ROWB + g * 16,
             bsrc + (size_t)row * (KPAD * 2) + g * 16);
    }
    asm volatile("cp.async.commit_group;" ::: "memory");
}

// ---------------------------------------------------------------------------
// main: 128x128 tile, 4 warps (64x64), BK=32, 3-stage (wait_group 1),
// refill AFTER compute (R8 verbatim)
// ---------------------------------------------------------------------------
__global__ void __launch_bounds__(128) ntxent_hmma() {
    extern __shared__ char smem[];
    const uint32_t sbase = smem_u32(smem);

    const int tid  = threadIdx.x;
    const int lane = tid & 31;
    const int wid  = tid >> 5;
    const int wm   = wid >> 1;
    const int wn   = wid & 1;
    const int m0   = blockIdx.y * BM;
    const int n0   = blockIdx.x * BN;

    float acc[4][8][4];
    #pragma unroll
    for (int i = 0; i < 4; i++)
        #pragma unroll
        for (int j = 0; j < 8; j++)
            #pragma unroll
            for (int q = 0; q < 4; q++) acc[i][j][q] = 0.f;

    const int a_row  = lane & 15;
    const int a_koff = ((lane >> 4) & 1) * 16;
    const int b_n    = (lane & 7) | ((lane >> 1) & 8);
    const int b_koff = ((lane >> 3) & 1) * 16;
    const uint32_t aBase = sbase + (wm * 64 + a_row) * ROWB + a_koff;
    const uint32_t bBase = sbase + BM * ROWB + (wn * 64 + b_n) * ROWB + b_koff;

    load_stage(sbase,               m0, n0, 0,  tid);
    load_stage(sbase + STAGE_BYTES, m0, n0, BK, tid);

    uint32_t soff = 0;
    uint32_t loff = 2 * STAGE_BYTES;
    int      lk   = 2 * BK;

    for (int c = 0; c < NITER; c++) {
        if (c < NITER - 1) asm volatile("cp.async.wait_group 1;" ::: "memory");
        else               asm volatile("cp.async.wait_group 0;" ::: "memory");
        __syncthreads();

        #pragma unroll
        for (int ks = 0; ks < 2; ks++) {
            const uint32_t koff = soff + ks * 32;

            uint32_t afrag[4][4];
            #pragma unroll
            for (int mi = 0; mi < 4; mi++)
                ldsm_x4(afrag[mi], aBase + koff + mi * (16 * ROWB));

            uint32_t bfrag[4][4];
            #pragma unroll
            for (int np = 0; np < 4; np++)
                ldsm_x4(bfrag[np], bBase + koff + np * (16 * ROWB));

            #pragma unroll
            for (int mi = 0; mi < 4; mi++)
                #pragma unroll
                for (int np = 0; np < 4; np++) {
                    mma_bf16(acc[mi][np * 2 + 0], afrag[mi],
                             bfrag[np][0], bfrag[np][1]);
                    mma_bf16(acc[mi][np * 2 + 1], afrag[mi],
                             bfrag[np][2], bfrag[np][3]);
                }
        }

        if (c + 2 < NITER) {
            load_stage(sbase + loff, m0, n0, lk, tid);
            lk += BK;
            loff += STAGE_BYTES;
            if (loff == STAGES * STAGE_BYTES) loff = 0;
        }
        soff += STAGE_BYTES;
        if (soff == STAGES * STAGE_BYTES) soff = 0;
    }

    // ---- epilogue: per-row sum of exp(4*S) ----
    float esum[8];
    #pragma unroll
    for (int q = 0; q < 8; q++) esum[q] = 0.f;

    #pragma unroll
    for (int mi = 0; mi < 4; mi++)
        #pragma unroll
        for (int nt = 0; nt < 8; nt++) {
            const float* cc = acc[mi][nt];
            esum[mi * 2 + 0] += __expf(INV_TEMP * cc[0]) + __expf(INV_TEMP * cc[1]);
            esum[mi * 2 + 1] += __expf(INV_TEMP * cc[2]) + __expf(INV_TEMP * cc[3]);
        }
    #pragma unroll
    for (int q = 0; q < 8; q++)
        #pragma unroll
        for (int o = 1; o < 4; o <<= 1)
            esum[q] += __shfl_xor_sync(0xffffffffu, esum[q], o);
    if ((lane & 3) == 0) {
        #pragma unroll
        for (int q = 0; q < 8; q++) {
            const int row = m0 + wm * 64 + (q >> 1) * 16 + (q & 1) * 8 + (lane >> 2);
            atomicAdd(&g_sumexp[row], esum[q]);
        }
    }
}

// ---------------------------------------------------------------------------
// finalize (R14 float2 version): rowsum fused; one warp per row
// ---------------------------------------------------------------------------
__global__ void __launch_bounds__(256) ntxent_finalize(const float* __restrict__ A,
                                                       float* __restrict__ out) {
    const int warp = threadIdx.x >> 5;
    const int lane = threadIdx.x & 31;
    const int row  = blockIdx.x * 8 + warp;

    const float2* ar2 = (const float2*)(A + (size_t)row * D_SIZE);
    const float2* q2  = (const float2*)g_q;
    float d0 = 0.f, d1 = 0.f;
    for (int c2 = lane; c2 < D2; c2 += 32) {
        float2 av = ar2[c2], qv = q2[c2];
        d0 = fmaf(av.x, qv.x, d0);
        d1 = fmaf(av.y, qv.y, d1);
    }
    float d = d0 + d1;
    #pragma unroll
    for (int o = 16; o; o >>= 1) d += __shfl_xor_sync(0xffffffffu, d, o);

    float loss = 0.f, pos = 0.f, neg = 0.f;
    if (lane == 0) {
        const float diag = g_diag[row];
        const float sumS = d * g_rna[row];
        loss = logf(g_sumexp[row]) - INV_TEMP * diag;
        pos  = diag;
        neg  = (sumS - diag) * (1.0f / (float)(B_SIZE - 1));
    }

    __shared__ float sl[8], sp[8], sn[8];
    if (lane == 0) { sl[warp] = loss; sp[warp] = pos; sn[warp] = neg; }
    __syncthreads();
    if (threadIdx.x == 0) {
        float tl = 0.f, tp = 0.f, tg = 0.f;
        #pragma unroll
        for (int w = 0; w < 8; w++) { tl += sl[w]; tp += sp[w]; tg += sn[w]; }
        const float invB = 1.0f / (float)B_SIZE;
        atomicAdd(out + 0, tl * invB);
        atomicAdd(out + 1, tp * invB);
        atomicAdd(out + 2, tg * invB);
    }
}

// ---------------------------------------------------------------------------
extern "C" void kernel_launch(void* const* d_in, const int* in_sizes, int n_in,
                              void* d_out, int out_size) {
    const float* A = (const float*)d_in[0];
    const float* P = (const float*)d_in[1];
    float* out = (float*)d_out;

    cudaFuncSetAttribute(ntxent_hmma,
                         cudaFuncAttributeMaxDynamicSharedMemorySize, SMEM_BYTES);

    ntxent_zeroq<<<1, 1024>>>();
    ntxent_prep<<<B_SIZE / 8, 256>>>(A, P, out);

    dim3 gg(B_SIZE / BN, B_SIZE / BM);   // (64, 64)
    ntxent_hmma<<<gg, 128, SMEM_BYTES>>>();

    ntxent_finalize<<<B_SIZE / 8, 256>>>(A, out);
}